// round 8
// baseline (speedup 1.0000x reference)
#include <cuda_runtime.h>
#include <cuda_fp16.h>
#include <cstddef>

// Problem constants (fixed by the reference)
#define NN    20000   // nodes
#define INF   256     // in feats
#define NH    8       // heads
#define HF1   64      // layer1 per-head channels
#define OUTC  32      // layer2 per-head channels
#define EMAX  700000  // >= E + NN self loops (640000 + 20000)

// ---------------------------------------------------------------------------
// Static device scratch (no allocations allowed)
// ---------------------------------------------------------------------------
__device__ float  g_h1[NN * NH * HF1];    // 40.96 MB  projected features L1 (fp32)
__device__ __half g_h1h[NN * NH * HF1];   // 20.48 MB  fp16 mirror for gather
__device__ float  g_hmid[NN * HF1];       // layer-1 output (mean+bias+relu)
__device__ float  g_h2[NN * NH * OUTC];   // 20.48 MB  projected features L2 (fp32)
__device__ __half g_h2h[NN * NH * OUTC];  // 10.24 MB  fp16 mirror for gather
__device__ float  g_asrc1[NN * NH];
__device__ float  g_adst1[NN * NH];
__device__ float  g_asrc2[NN * NH];
__device__ float  g_adst2[NN * NH];
__device__ int    g_rowptr[NN + 1];
__device__ int    g_deg[NN];
__device__ int    g_rank[EMAX];
__device__ int    g_srcsorted[EMAX];

// ---------------------------------------------------------------------------
// Packed f32x2 FMA helpers (doubles FP32 throughput on sm_103a:
// FFMA rt_SMSP=2, FFMA2 gives 2 results per issue)
// ---------------------------------------------------------------------------
__device__ __forceinline__ unsigned long long pack2(float x) {
    unsigned long long r;
    asm("mov.b64 %0, {%1, %1};" : "=l"(r) : "f"(x));
    return r;
}
__device__ __forceinline__ void ffma2(unsigned long long& d,
                                      unsigned long long a,
                                      unsigned long long b) {
    asm("fma.rn.f32x2 %0, %1, %2, %0;" : "+l"(d) : "l"(a), "l"(b));
}
__device__ __forceinline__ float2 unpack2(unsigned long long v) {
    float2 f;
    asm("mov.b64 {%0, %1}, %2;" : "=f"(f.x), "=f"(f.y) : "l"(v));
    return f;
}

// ---------------------------------------------------------------------------
// FP32 SGEMM: C[M,Nc] = A[M,K] @ B[K,Nc], BM=BN=128, BK=16, 256 thr, 8x8/thr
// split-tile (4+4) register layout, FFMA2 inner product.
// Requires: K % 16 == 0, Nc % 128 == 0. Row guard on M.
// ---------------------------------------------------------------------------
__global__ __launch_bounds__(256, 2)
void gemm_kernel(const float* __restrict__ A, const float* __restrict__ B,
                 float* __restrict__ C, int M, int K, int Nc)
{
    __shared__ __align__(16) float As[16][132];  // [k][m], padded
    __shared__ __align__(16) float Bs[16][128];  // [k][n]

    const int tid = threadIdx.x;
    const int bm = blockIdx.y * 128;
    const int bn = blockIdx.x * 128;

    const int a_c4 = (tid & 3) * 4;   // k-offset of this thread's A float4
    const int a_r  = tid >> 2;        // 0..63 (two row passes: +0, +64)
    const int b_n  = (tid & 31) * 4;  // n-offset of B float4
    const int b_k  = tid >> 5;        // 0..7 (two k passes: +0, +8)

    const int tx = tid & 15;          // 16 col groups
    const int ty = tid >> 4;          // 16 row groups

    unsigned long long acc[8][4];
#pragma unroll
    for (int i = 0; i < 8; i++)
#pragma unroll
        for (int j = 0; j < 4; j++) acc[i][j] = 0ULL;  // == {+0.f,+0.f}

    for (int k0 = 0; k0 < K; k0 += 16) {
        float4 av[2], bv[2];
#pragma unroll
        for (int rr = 0; rr < 2; rr++) {
            int grow = bm + a_r + rr * 64;
            av[rr] = make_float4(0.f, 0.f, 0.f, 0.f);
            if (grow < M)
                av[rr] = *(const float4*)&A[(size_t)grow * K + k0 + a_c4];
            bv[rr] = *(const float4*)&B[(size_t)(k0 + b_k + rr * 8) * Nc + bn + b_n];
        }
        __syncthreads();  // protect previous iteration's readers
#pragma unroll
        for (int rr = 0; rr < 2; rr++) {
            int r = a_r + rr * 64;
            As[a_c4 + 0][r] = av[rr].x;
            As[a_c4 + 1][r] = av[rr].y;
            As[a_c4 + 2][r] = av[rr].z;
            As[a_c4 + 3][r] = av[rr].w;
            *(float4*)&Bs[b_k + rr * 8][b_n] = bv[rr];
        }
        __syncthreads();

#pragma unroll
        for (int kk = 0; kk < 16; kk++) {
            float4 alo = *(const float4*)&As[kk][ty * 4];
            float4 ahi = *(const float4*)&As[kk][64 + ty * 4];
            ulonglong2 blo = *(const ulonglong2*)&Bs[kk][tx * 4];
            ulonglong2 bhi = *(const ulonglong2*)&Bs[kk][64 + tx * 4];
            unsigned long long a2[8] = {
                pack2(alo.x), pack2(alo.y), pack2(alo.z), pack2(alo.w),
                pack2(ahi.x), pack2(ahi.y), pack2(ahi.z), pack2(ahi.w)};
            unsigned long long b2[4] = {blo.x, blo.y, bhi.x, bhi.y};
#pragma unroll
            for (int i = 0; i < 8; i++)
#pragma unroll
                for (int j = 0; j < 4; j++) ffma2(acc[i][j], a2[i], b2[j]);
        }
    }

#pragma unroll
    for (int i = 0; i < 8; i++) {
        int r = (i < 4) ? (ty * 4 + i) : (64 + ty * 4 + (i - 4));
        int grow = bm + r;
        if (grow < M) {
            float2 p0 = unpack2(acc[i][0]);
            float2 p1 = unpack2(acc[i][1]);
            *(float4*)&C[(size_t)grow * Nc + bn + tx * 4] =
                make_float4(p0.x, p0.y, p1.x, p1.y);
            p0 = unpack2(acc[i][2]);
            p1 = unpack2(acc[i][3]);
            *(float4*)&C[(size_t)grow * Nc + bn + 64 + tx * 4] =
                make_float4(p0.x, p0.y, p1.x, p1.y);
        }
    }
}

// ---------------------------------------------------------------------------
// Per-node attention logits + fp16 mirror write.
// asrc[n,h] = <feat[n,h,:], att_s[h,:]>, same for dst.
// block = node, warp = head. Logit layout [NN][NH] (one 32B sector / node).
// ---------------------------------------------------------------------------
__global__ void att_kernel(const float* __restrict__ feat,
                           __half* __restrict__ feat_h,
                           const float* __restrict__ att_s,
                           const float* __restrict__ att_d,
                           float* __restrict__ osrc,
                           float* __restrict__ odst, int CH)
{
    int n = blockIdx.x;
    int h = threadIdx.x >> 5;
    int lane = threadIdx.x & 31;
    const size_t base = (size_t)n * NH * CH + h * CH;
    const float* frow = feat + base;
    __half* hrow = feat_h + base;
    const float* as = att_s + h * CH;
    const float* ad = att_d + h * CH;
    float ssum = 0.f, dsum = 0.f;
    for (int c = lane; c < CH; c += 32) {
        float v = frow[c];
        hrow[c] = __float2half(v);
        ssum += v * as[c];
        dsum += v * ad[c];
    }
#pragma unroll
    for (int o = 16; o; o >>= 1) {
        ssum += __shfl_xor_sync(0xffffffffu, ssum, o);
        dsum += __shfl_xor_sync(0xffffffffu, dsum, o);
    }
    if (lane == 0) {
        osrc[n * NH + h] = ssum;
        odst[n * NH + h] = dsum;
    }
}

// ---------------------------------------------------------------------------
// CSR build: deg init=1 (self loop slot 0); hist atomic also yields per-edge
// rank (old count), so the final scatter is atomic-free.
// ---------------------------------------------------------------------------
__global__ void init_deg_kernel()
{
    int i = blockIdx.x * blockDim.x + threadIdx.x;
    if (i < NN) g_deg[i] = 1;  // self loop occupies rank 0
}

__global__ void histrank_kernel(const int* __restrict__ dst, int E)
{
    int i = blockIdx.x * blockDim.x + threadIdx.x;
    if (i < E) {
        int r = atomicAdd(&g_deg[dst[i]], 1);
        g_rank[i] = r;
    }
}

// Single-block exclusive scan of g_deg[NN] -> g_rowptr.
// 1024 threads x 20 items/thread (20480 >= NN).
__global__ void scan_fused_kernel()
{
    __shared__ int wsum[32];
    const int tid = threadIdx.x;
    const int lane = tid & 31;
    const int w = tid >> 5;
    const int base = tid * 20;

    int vals[20];
    int s = 0;
#pragma unroll
    for (int k = 0; k < 20; k++) {
        int i = base + k;
        int v = (i < NN) ? g_deg[i] : 0;
        vals[k] = s;       // thread-local exclusive prefix
        s += v;
    }

    // block exclusive scan of per-thread sums
    int x = s;
#pragma unroll
    for (int o = 1; o < 32; o <<= 1) {
        int y = __shfl_up_sync(0xffffffffu, x, o);
        if (lane >= o) x += y;
    }
    if (lane == 31) wsum[w] = x;
    __syncthreads();
    if (tid < 32) {
        int ww = wsum[tid];
#pragma unroll
        for (int o = 1; o < 32; o <<= 1) {
            int y = __shfl_up_sync(0xffffffffu, ww, o);
            if (tid >= o) ww += y;
        }
        wsum[tid] = ww;
    }
    __syncthreads();
    int excl = (x - s) + ((w > 0) ? wsum[w - 1] : 0);

#pragma unroll
    for (int k = 0; k < 20; k++) {
        int i = base + k;
        if (i < NN) g_rowptr[i] = excl + vals[k];
    }
    if (tid == 1023) g_rowptr[NN] = excl + s;  // total
}

__global__ void scatter_kernel(const int* __restrict__ src,
                               const int* __restrict__ dst, int E)
{
    int i = blockIdx.x * blockDim.x + threadIdx.x;
    if (i < E) {
        g_srcsorted[g_rowptr[dst[i]] + g_rank[i]] = src[i];
    } else if (i < E + NN) {
        int n = i - E;
        g_srcsorted[g_rowptr[n]] = n;  // self loop at rank 0
    }
}

// ---------------------------------------------------------------------------
// GAT aggregation (single pass, no segment max: logits are O(10) so plain
// exp is numerically safe and mathematically identical after normalization).
// block = dst node, 256 threads. Feature gather reads the fp16 mirror.
//   Phase A (per 32-edge chunk): thread (e = tid/8, h = tid%8) computes
//     p = exp(leaky(asrc[s][h] + adst[n][h])) -> smem (full-sector logit read).
//   Phase B: warp w = head w gathers feat_h[src] rows, acc += p * h.
//   Epilogue: normalize by 1/ssum, mean over heads, bias, optional relu.
// ---------------------------------------------------------------------------
template <int CH>
__global__ __launch_bounds__(256)
void agg_kernel(const __half* __restrict__ feat_h,    // [NN, NH*CH] fp16
                const float* __restrict__ asrc,       // [NN][NH]
                const float* __restrict__ adst_arr,   // [NN][NH]
                const float* __restrict__ bias,       // [CH]
                float* __restrict__ outp,             // [NN, CH]
                int do_relu)
{
    const int n    = blockIdx.x;
    const int tid  = threadIdx.x;
    const int w    = tid >> 5;   // warp == head in phase B
    const int lane = tid & 31;
    const int eh_e = tid >> 3;   // edge slot in phase A (0..31)
    const int eh_h = tid & 7;    // head in phase A

    const int beg = g_rowptr[n];
    const int end = g_rowptr[n + 1];

    __shared__ float p_buf[32][8];
    __shared__ int   sidx[32];
    __shared__ float wsum[8][8];   // [warp][head]
    __shared__ float sinv[8];
    __shared__ float sacc[NH * CH];

    const float adst = adst_arr[n * NH + eh_h];

    float ssum = 0.f;
    float acc0 = 0.f, acc1 = 0.f;

    for (int c0 = beg; c0 < end; c0 += 32) {
        const int cnt = min(32, end - c0);

        // ---- phase A: per-edge-per-head softmax numerator ----
        if (eh_e < cnt) {
            int s = g_srcsorted[c0 + eh_e];
            if (eh_h == 0) sidx[eh_e] = s;
            float e = asrc[s * NH + eh_h] + adst;
            e = (e > 0.f) ? e : 0.2f * e;
            float p = __expf(e);
            p_buf[eh_e][eh_h] = p;
            ssum += p;
        }
        __syncthreads();

        // ---- phase B: weighted fp16 feature gather, warp w = head w ----
        int t = 0;
        for (; t + 4 <= cnt; t += 4) {
            float pj0 = p_buf[t + 0][w];
            float pj1 = p_buf[t + 1][w];
            float pj2 = p_buf[t + 2][w];
            float pj3 = p_buf[t + 3][w];
            int s0 = sidx[t + 0], s1 = sidx[t + 1];
            int s2 = sidx[t + 2], s3 = sidx[t + 3];
            if (CH == 64) {
                float2 v0 = __half22float2(*(const __half2*)&feat_h[(size_t)s0 * (NH*CH) + w*CH + lane*2]);
                float2 v1 = __half22float2(*(const __half2*)&feat_h[(size_t)s1 * (NH*CH) + w*CH + lane*2]);
                float2 v2 = __half22float2(*(const __half2*)&feat_h[(size_t)s2 * (NH*CH) + w*CH + lane*2]);
                float2 v3 = __half22float2(*(const __half2*)&feat_h[(size_t)s3 * (NH*CH) + w*CH + lane*2]);
                acc0 = fmaf(pj0, v0.x, acc0); acc1 = fmaf(pj0, v0.y, acc1);
                acc0 = fmaf(pj1, v1.x, acc0); acc1 = fmaf(pj1, v1.y, acc1);
                acc0 = fmaf(pj2, v2.x, acc0); acc1 = fmaf(pj2, v2.y, acc1);
                acc0 = fmaf(pj3, v3.x, acc0); acc1 = fmaf(pj3, v3.y, acc1);
            } else {
                float v0 = __half2float(feat_h[(size_t)s0 * (NH*CH) + w*CH + lane]);
                float v1 = __half2float(feat_h[(size_t)s1 * (NH*CH) + w*CH + lane]);
                float v2 = __half2float(feat_h[(size_t)s2 * (NH*CH) + w*CH + lane]);
                float v3 = __half2float(feat_h[(size_t)s3 * (NH*CH) + w*CH + lane]);
                acc0 = fmaf(pj0, v0, acc0);
                acc0 = fmaf(pj1, v1, acc0);
                acc0 = fmaf(pj2, v2, acc0);
                acc0 = fmaf(pj3, v3, acc0);
            }
        }
        for (; t < cnt; t++) {
            float pj = p_buf[t][w];
            int sj = sidx[t];
            if (CH == 64) {
                float2 hv = __half22float2(*(const __half2*)&feat_h[(size_t)sj * (NH*CH) + w*CH + lane*2]);
                acc0 = fmaf(pj, hv.x, acc0);
                acc1 = fmaf(pj, hv.y, acc1);
            } else {
                float hv = __half2float(feat_h[(size_t)sj * (NH*CH) + w*CH + lane]);
                acc0 = fmaf(pj, hv, acc0);
            }
        }
        __syncthreads();
    }

    // ---- reduce ssum by head: lanes {l, l^8, l^16, l^24} share head l&7 ----
    ssum += __shfl_xor_sync(0xffffffffu, ssum, 8);
    ssum += __shfl_xor_sync(0xffffffffu, ssum, 16);
    if (lane < 8) wsum[w][lane] = ssum;
    __syncthreads();
    if (tid < 8) {
        float s = 0.f;
#pragma unroll
        for (int ww = 0; ww < 8; ww++) s += wsum[ww][tid];
        sinv[tid] = 1.0f / s;
    }
    __syncthreads();

    // ---- epilogue: normalize, mean over heads, bias, (relu) ----
    float inv = sinv[w];
    if (CH == 64) {
        sacc[w * CH + lane * 2]     = acc0 * inv;
        sacc[w * CH + lane * 2 + 1] = acc1 * inv;
    } else {
        sacc[w * CH + lane] = acc0 * inv;
    }
    __syncthreads();
    if (tid < CH) {
        float v = 0.f;
#pragma unroll
        for (int hh = 0; hh < NH; hh++) v += sacc[hh * CH + tid];
        v = v * 0.125f + bias[tid];
        if (do_relu) v = fmaxf(v, 0.f);
        outp[(size_t)n * CH + tid] = v;
    }
}

// ---------------------------------------------------------------------------
// Launch (ordered so the 4th launch is gemm_kernel for the ncu window)
// ---------------------------------------------------------------------------
extern "C" void kernel_launch(void* const* d_in, const int* in_sizes, int n_in,
                              void* d_out, int out_size)
{
    const float* x   = (const float*)d_in[0];
    const int*   ei  = (const int*)d_in[1];
    const float* W1  = (const float*)d_in[2];
    const float* as1 = (const float*)d_in[3];
    const float* ad1 = (const float*)d_in[4];
    const float* b1  = (const float*)d_in[5];
    const float* W2  = (const float*)d_in[6];
    const float* as2 = (const float*)d_in[7];
    const float* ad2 = (const float*)d_in[8];
    const float* b2  = (const float*)d_in[9];
    float* out = (float*)d_out;

    const int E = in_sizes[1] / 2;
    const int* esrc = ei;
    const int* edst = ei + E;

    float  *p_h1, *p_hmid, *p_h2;
    __half *p_h1h, *p_h2h;
    float  *p_asrc1, *p_adst1, *p_asrc2, *p_adst2;
    cudaGetSymbolAddress((void**)&p_h1,    g_h1);
    cudaGetSymbolAddress((void**)&p_h1h,   g_h1h);
    cudaGetSymbolAddress((void**)&p_hmid,  g_hmid);
    cudaGetSymbolAddress((void**)&p_h2,    g_h2);
    cudaGetSymbolAddress((void**)&p_h2h,   g_h2h);
    cudaGetSymbolAddress((void**)&p_asrc1, g_asrc1);
    cudaGetSymbolAddress((void**)&p_adst1, g_adst1);
    cudaGetSymbolAddress((void**)&p_asrc2, g_asrc2);
    cudaGetSymbolAddress((void**)&p_adst2, g_adst2);

    // ---- CSR build prefix + big GEMM early (gemm1 = 4th launch for ncu) ----
    init_deg_kernel<<<(NN + 255) / 256, 256>>>();            // 0
    histrank_kernel<<<(E + 255) / 256, 256>>>(edst, E);      // 1
    scan_fused_kernel<<<1, 1024>>>();                        // 2
    {
        dim3 grid((NH * HF1) / 128, (NN + 127) / 128);       // 3  <- profiled
        gemm_kernel<<<grid, 256>>>(x, W1, p_h1, NN, INF, NH * HF1);
    }
    scatter_kernel<<<(E + NN + 255) / 256, 256>>>(esrc, edst, E);  // 4

    // ---- layer 1 ----
    att_kernel<<<NN, 256>>>(p_h1, p_h1h, as1, ad1, p_asrc1, p_adst1, HF1);
    agg_kernel<HF1><<<NN, 256>>>(p_h1h, p_asrc1, p_adst1, b1, p_hmid, 1);

    // ---- layer 2 ----
    {
        dim3 grid((NH * OUTC) / 128, (NN + 127) / 128);
        gemm_kernel<<<grid, 256>>>(p_hmid, W2, p_h2, NN, HF1, NH * OUTC);
    }
    att_kernel<<<NN, 256>>>(p_h2, p_h2h, as2, ad2, p_asrc2, p_adst2, OUTC);
    agg_kernel<OUTC><<<NN, 256>>>(p_h2h, p_asrc2, p_adst2, b2, out, 0);
}

// round 9
// speedup vs baseline: 1.2543x; 1.2543x over previous
#include <cuda_runtime.h>
#include <cuda_fp16.h>
#include <cstddef>

// Problem constants (fixed by the reference)
#define NN    20000   // nodes
#define INF   256     // in feats
#define NH    8       // heads
#define HF1   64      // layer1 per-head channels
#define OUTC  32      // layer2 per-head channels
#define EMAX  700000  // >= E + NN self loops (640000 + 20000)

// ---------------------------------------------------------------------------
// Static device scratch (no allocations allowed)
// ---------------------------------------------------------------------------
__device__ __half g_h1h[NN * NH * HF1];   // 20.48 MB projected features L1 (fp16)
__device__ float  g_hmid[NN * HF1];       // layer-1 output (mean+bias+relu)
__device__ __half g_h2h[NN * NH * OUTC];  // 10.24 MB projected features L2 (fp16)
__device__ float  g_asrc1[NN * NH];
__device__ float  g_adst1[NN * NH];
__device__ float  g_asrc2[NN * NH];
__device__ float  g_adst2[NN * NH];
__device__ int    g_rowptr[NN + 1];
__device__ int    g_deg[NN];
__device__ int    g_rank[EMAX];
__device__ int    g_srcsorted[EMAX];

// ---------------------------------------------------------------------------
// Tensor-core helpers: tf32 m16n8k8 mma + fp32->tf32 convert
// ---------------------------------------------------------------------------
__device__ __forceinline__ unsigned f2tf(float x) {
    unsigned r;
    asm("cvt.rna.tf32.f32 %0, %1;" : "=r"(r) : "f"(x));
    return r;
}
__device__ __forceinline__ void mma8(float* c, const unsigned* a, const unsigned* b) {
    asm volatile(
        "mma.sync.aligned.m16n8k8.row.col.f32.tf32.tf32.f32 "
        "{%0,%1,%2,%3}, {%4,%5,%6,%7}, {%8,%9}, {%0,%1,%2,%3};"
        : "+f"(c[0]), "+f"(c[1]), "+f"(c[2]), "+f"(c[3])
        : "r"(a[0]), "r"(a[1]), "r"(a[2]), "r"(a[3]), "r"(b[0]), "r"(b[1]));
}

// ---------------------------------------------------------------------------
// TF32 tensor-core GEMM: C[M,Nc](fp16) = A[M,K](fp32) @ B[K,Nc](fp32)
// BM=BN=128, BK=32, 256 threads, warp grid 2(m) x 4(n), warp tile 64x32.
// smem layout: word addr = k*136 + (m ^ (((k>>2)&7)<<2))  — bank-conflict-free
// for both the transposed A stores and all fragment reads (verified).
// Requires K % 32 == 0, Nc % 128 == 0. Row guard on M.
// ---------------------------------------------------------------------------
#define SAS 136
__global__ __launch_bounds__(256, 2)
void gemm_tc_kernel(const float* __restrict__ A, const float* __restrict__ B,
                    __half* __restrict__ C, int M, int K, int Nc)
{
    __shared__ unsigned As[32 * SAS];
    __shared__ unsigned Bs[32 * SAS];

    const int tid  = threadIdx.x;
    const int bm   = blockIdx.y * 128;
    const int bn   = blockIdx.x * 128;
    const int lane = tid & 31;
    const int wid  = tid >> 5;
    const int warp_m = wid & 1;    // 0..1 -> 64 rows each
    const int warp_n = wid >> 1;   // 0..3 -> 32 cols each
    const int g = lane >> 2;       // 0..7
    const int t = lane & 3;        // 0..3

    // A tile load mapping (coalesced: 4 rows x 128B per warp)
    const int a_r0 = tid >> 3;        // 0..31
    const int a_q  = tid & 7;         // k-group (float4 col block)
    const int a_c4 = a_q * 4;
    // B tile load mapping (coalesced: full 512B rows)
    const int b_k0 = tid >> 5;        // 0..7
    const int b_n4 = (tid & 31) * 4;

    float acc[4][4][4];
#pragma unroll
    for (int i = 0; i < 4; i++)
#pragma unroll
        for (int j = 0; j < 4; j++)
#pragma unroll
            for (int v = 0; v < 4; v++) acc[i][j][v] = 0.f;

    for (int k0 = 0; k0 < K; k0 += 32) {
        float4 av[4], bv[4];
#pragma unroll
        for (int rr = 0; rr < 4; rr++) {
            int grow = bm + a_r0 + rr * 32;
            av[rr] = make_float4(0.f, 0.f, 0.f, 0.f);
            if (grow < M)
                av[rr] = *(const float4*)&A[(size_t)grow * K + k0 + a_c4];
            bv[rr] = *(const float4*)&B[(size_t)(k0 + b_k0 + rr * 8) * Nc + bn + b_n4];
        }
        __syncthreads();  // protect previous iteration's readers
#pragma unroll
        for (int rr = 0; rr < 4; rr++) {
            int r = a_r0 + rr * 32;
            // A transposed store with XOR swizzle (conflict-free)
            As[(a_c4 + 0) * SAS + (r ^ (a_q << 2))] = f2tf(av[rr].x);
            As[(a_c4 + 1) * SAS + (r ^ (a_q << 2))] = f2tf(av[rr].y);
            As[(a_c4 + 2) * SAS + (r ^ (a_q << 2))] = f2tf(av[rr].z);
            As[(a_c4 + 3) * SAS + (r ^ (a_q << 2))] = f2tf(av[rr].w);
            int kb = b_k0 + rr * 8;
            int q  = (kb >> 2) & 7;
            *(uint4*)&Bs[kb * SAS + (b_n4 ^ (q << 2))] =
                make_uint4(f2tf(bv[rr].x), f2tf(bv[rr].y), f2tf(bv[rr].z), f2tf(bv[rr].w));
        }
        __syncthreads();

#pragma unroll
        for (int kk = 0; kk < 4; kk++) {
            const int k8 = kk * 8;
            const int qa = (k8 >> 2) & 7;      // = 2*kk (even)
            const int qb = qa + 1;
            unsigned af[4][4];
#pragma unroll
            for (int mt = 0; mt < 4; mt++) {
                int rm = warp_m * 64 + mt * 16 + g;
                af[mt][0] = As[(k8 + t) * SAS + (rm ^ (qa << 2))];
                af[mt][1] = As[(k8 + t) * SAS + ((rm + 8) ^ (qa << 2))];
                af[mt][2] = As[(k8 + t + 4) * SAS + (rm ^ (qb << 2))];
                af[mt][3] = As[(k8 + t + 4) * SAS + ((rm + 8) ^ (qb << 2))];
            }
            unsigned bf[4][2];
#pragma unroll
            for (int nt = 0; nt < 4; nt++) {
                int cn = warp_n * 32 + nt * 8 + g;
                bf[nt][0] = Bs[(k8 + t) * SAS + (cn ^ (qa << 2))];
                bf[nt][1] = Bs[(k8 + t + 4) * SAS + (cn ^ (qb << 2))];
            }
#pragma unroll
            for (int mt = 0; mt < 4; mt++)
#pragma unroll
                for (int nt = 0; nt < 4; nt++)
                    mma8(acc[mt][nt], af[mt], bf[nt]);
        }
    }

    // epilogue: fp16 stores (half2 per c-pair; cols 2t,2t+1 contiguous)
#pragma unroll
    for (int mt = 0; mt < 4; mt++) {
        int row0 = bm + warp_m * 64 + mt * 16 + g;
#pragma unroll
        for (int nt = 0; nt < 4; nt++) {
            int col = bn + warp_n * 32 + nt * 8 + 2 * t;
            if (row0 < M)
                *(__half2*)&C[(size_t)row0 * Nc + col] =
                    __floats2half2_rn(acc[mt][nt][0], acc[mt][nt][1]);
            if (row0 + 8 < M)
                *(__half2*)&C[(size_t)(row0 + 8) * Nc + col] =
                    __floats2half2_rn(acc[mt][nt][2], acc[mt][nt][3]);
        }
    }
}

// ---------------------------------------------------------------------------
// Per-node attention logits from the fp16 features.
// asrc[n,h] = <feat[n,h,:], att_s[h,:]>, same for dst.
// block = node, warp = head. Logit layout [NN][NH].
// ---------------------------------------------------------------------------
__global__ void att_kernel(const __half* __restrict__ feat_h,
                           const float* __restrict__ att_s,
                           const float* __restrict__ att_d,
                           float* __restrict__ osrc,
                           float* __restrict__ odst, int CH)
{
    int n = blockIdx.x;
    int h = threadIdx.x >> 5;
    int lane = threadIdx.x & 31;
    const __half* frow = feat_h + (size_t)n * NH * CH + h * CH;
    const float* as = att_s + h * CH;
    const float* ad = att_d + h * CH;
    float ssum = 0.f, dsum = 0.f;
    for (int c = lane * 2; c < CH; c += 64) {
        float2 v = __half22float2(*(const __half2*)&frow[c]);
        ssum += v.x * as[c] + v.y * as[c + 1];
        dsum += v.x * ad[c] + v.y * ad[c + 1];
    }
#pragma unroll
    for (int o = 16; o; o >>= 1) {
        ssum += __shfl_xor_sync(0xffffffffu, ssum, o);
        dsum += __shfl_xor_sync(0xffffffffu, dsum, o);
    }
    if (lane == 0) {
        osrc[n * NH + h] = ssum;
        odst[n * NH + h] = dsum;
    }
}

// ---------------------------------------------------------------------------
// CSR build: deg init=1 (self loop slot 0); hist atomic also yields per-edge
// rank (old count), so the final scatter is atomic-free.
// ---------------------------------------------------------------------------
__global__ void init_deg_kernel()
{
    int i = blockIdx.x * blockDim.x + threadIdx.x;
    if (i < NN) g_deg[i] = 1;  // self loop occupies rank 0
}

__global__ void histrank_kernel(const int* __restrict__ dst, int E)
{
    int i = blockIdx.x * blockDim.x + threadIdx.x;
    if (i < E) {
        int r = atomicAdd(&g_deg[dst[i]], 1);
        g_rank[i] = r;
    }
}

// Single-block exclusive scan of g_deg[NN] -> g_rowptr.
// 1024 threads x 20 items/thread (20480 >= NN).
__global__ void scan_fused_kernel()
{
    __shared__ int wsum[32];
    const int tid = threadIdx.x;
    const int lane = tid & 31;
    const int w = tid >> 5;
    const int base = tid * 20;

    int vals[20];
    int s = 0;
#pragma unroll
    for (int k = 0; k < 20; k++) {
        int i = base + k;
        int v = (i < NN) ? g_deg[i] : 0;
        vals[k] = s;       // thread-local exclusive prefix
        s += v;
    }

    int x = s;
#pragma unroll
    for (int o = 1; o < 32; o <<= 1) {
        int y = __shfl_up_sync(0xffffffffu, x, o);
        if (lane >= o) x += y;
    }
    if (lane == 31) wsum[w] = x;
    __syncthreads();
    if (tid < 32) {
        int ww = wsum[tid];
#pragma unroll
        for (int o = 1; o < 32; o <<= 1) {
            int y = __shfl_up_sync(0xffffffffu, ww, o);
            if (tid >= o) ww += y;
        }
        wsum[tid] = ww;
    }
    __syncthreads();
    int excl = (x - s) + ((w > 0) ? wsum[w - 1] : 0);

#pragma unroll
    for (int k = 0; k < 20; k++) {
        int i = base + k;
        if (i < NN) g_rowptr[i] = excl + vals[k];
    }
    if (tid == 1023) g_rowptr[NN] = excl + s;  // total
}

__global__ void scatter_kernel(const int* __restrict__ src,
                               const int* __restrict__ dst, int E)
{
    int i = blockIdx.x * blockDim.x + threadIdx.x;
    if (i < E) {
        g_srcsorted[g_rowptr[dst[i]] + g_rank[i]] = src[i];
    } else if (i < E + NN) {
        int n = i - E;
        g_srcsorted[g_rowptr[n]] = n;  // self loop at rank 0
    }
}

// ---------------------------------------------------------------------------
// GAT aggregation (single pass, no segment max: logits are O(10) so plain
// exp is numerically safe and identical after normalization).
// block = dst node, 256 threads. Feature gather reads fp16.
// ---------------------------------------------------------------------------
template <int CH>
__global__ __launch_bounds__(256)
void agg_kernel(const __half* __restrict__ feat_h,    // [NN, NH*CH] fp16
                const float* __restrict__ asrc,       // [NN][NH]
                const float* __restrict__ adst_arr,   // [NN][NH]
                const float* __restrict__ bias,       // [CH]
                float* __restrict__ outp,             // [NN, CH]
                int do_relu)
{
    const int n    = blockIdx.x;
    const int tid  = threadIdx.x;
    const int w    = tid >> 5;   // warp == head in phase B
    const int lane = tid & 31;
    const int eh_e = tid >> 3;   // edge slot in phase A (0..31)
    const int eh_h = tid & 7;    // head in phase A

    const int beg = g_rowptr[n];
    const int end = g_rowptr[n + 1];

    __shared__ float p_buf[32][8];
    __shared__ int   sidx[32];
    __shared__ float wsum[8][8];
    __shared__ float sinv[8];
    __shared__ float sacc[NH * CH];

    const float adst = adst_arr[n * NH + eh_h];

    float ssum = 0.f;
    float acc0 = 0.f, acc1 = 0.f;

    for (int c0 = beg; c0 < end; c0 += 32) {
        const int cnt = min(32, end - c0);

        // ---- phase A ----
        if (eh_e < cnt) {
            int s = g_srcsorted[c0 + eh_e];
            if (eh_h == 0) sidx[eh_e] = s;
            float e = asrc[s * NH + eh_h] + adst;
            e = (e > 0.f) ? e : 0.2f * e;
            float p = __expf(e);
            p_buf[eh_e][eh_h] = p;
            ssum += p;
        }
        __syncthreads();

        // ---- phase B ----
        int t = 0;
        for (; t + 4 <= cnt; t += 4) {
            float pj0 = p_buf[t + 0][w];
            float pj1 = p_buf[t + 1][w];
            float pj2 = p_buf[t + 2][w];
            float pj3 = p_buf[t + 3][w];
            int s0 = sidx[t + 0], s1 = sidx[t + 1];
            int s2 = sidx[t + 2], s3 = sidx[t + 3];
            if (CH == 64) {
                float2 v0 = __half22float2(*(const __half2*)&feat_h[(size_t)s0 * (NH*CH) + w*CH + lane*2]);
                float2 v1 = __half22float2(*(const __half2*)&feat_h[(size_t)s1 * (NH*CH) + w*CH + lane*2]);
                float2 v2 = __half22float2(*(const __half2*)&feat_h[(size_t)s2 * (NH*CH) + w*CH + lane*2]);
                float2 v3 = __half22float2(*(const __half2*)&feat_h[(size_t)s3 * (NH*CH) + w*CH + lane*2]);
                acc0 = fmaf(pj0, v0.x, acc0); acc1 = fmaf(pj0, v0.y, acc1);
                acc0 = fmaf(pj1, v1.x, acc0); acc1 = fmaf(pj1, v1.y, acc1);
                acc0 = fmaf(pj2, v2.x, acc0); acc1 = fmaf(pj2, v2.y, acc1);
                acc0 = fmaf(pj3, v3.x, acc0); acc1 = fmaf(pj3, v3.y, acc1);
            } else {
                float v0 = __half2float(feat_h[(size_t)s0 * (NH*CH) + w*CH + lane]);
                float v1 = __half2float(feat_h[(size_t)s1 * (NH*CH) + w*CH + lane]);
                float v2 = __half2float(feat_h[(size_t)s2 * (NH*CH) + w*CH + lane]);
                float v3 = __half2float(feat_h[(size_t)s3 * (NH*CH) + w*CH + lane]);
                acc0 = fmaf(pj0, v0, acc0);
                acc0 = fmaf(pj1, v1, acc0);
                acc0 = fmaf(pj2, v2, acc0);
                acc0 = fmaf(pj3, v3, acc0);
            }
        }
        for (; t < cnt; t++) {
            float pj = p_buf[t][w];
            int sj = sidx[t];
            if (CH == 64) {
                float2 hv = __half22float2(*(const __half2*)&feat_h[(size_t)sj * (NH*CH) + w*CH + lane*2]);
                acc0 = fmaf(pj, hv.x, acc0);
                acc1 = fmaf(pj, hv.y, acc1);
            } else {
                float hv = __half2float(feat_h[(size_t)sj * (NH*CH) + w*CH + lane]);
                acc0 = fmaf(pj, hv, acc0);
            }
        }
        __syncthreads();
    }

    // ---- reduce ssum by head ----
    ssum += __shfl_xor_sync(0xffffffffu, ssum, 8);
    ssum += __shfl_xor_sync(0xffffffffu, ssum, 16);
    if (lane < 8) wsum[w][lane] = ssum;
    __syncthreads();
    if (tid < 8) {
        float s = 0.f;
#pragma unroll
        for (int ww = 0; ww < 8; ww++) s += wsum[ww][tid];
        sinv[tid] = 1.0f / s;
    }
    __syncthreads();

    // ---- epilogue ----
    float inv = sinv[w];
    if (CH == 64) {
        sacc[w * CH + lane * 2]     = acc0 * inv;
        sacc[w * CH + lane * 2 + 1] = acc1 * inv;
    } else {
        sacc[w * CH + lane] = acc0 * inv;
    }
    __syncthreads();
    if (tid < CH) {
        float v = 0.f;
#pragma unroll
        for (int hh = 0; hh < NH; hh++) v += sacc[hh * CH + tid];
        v = v * 0.125f + bias[tid];
        if (do_relu) v = fmaxf(v, 0.f);
        outp[(size_t)n * CH + tid] = v;
    }
}

// ---------------------------------------------------------------------------
// Launch (4th launch = gemm1 for the ncu -s 5 -c 1 window)
// ---------------------------------------------------------------------------
extern "C" void kernel_launch(void* const* d_in, const int* in_sizes, int n_in,
                              void* d_out, int out_size)
{
    const float* x   = (const float*)d_in[0];
    const int*   ei  = (const int*)d_in[1];
    const float* W1  = (const float*)d_in[2];
    const float* as1 = (const float*)d_in[3];
    const float* ad1 = (const float*)d_in[4];
    const float* b1  = (const float*)d_in[5];
    const float* W2  = (const float*)d_in[6];
    const float* as2 = (const float*)d_in[7];
    const float* ad2 = (const float*)d_in[8];
    const float* b2  = (const float*)d_in[9];
    float* out = (float*)d_out;

    const int E = in_sizes[1] / 2;
    const int* esrc = ei;
    const int* edst = ei + E;

    __half *p_h1h, *p_h2h;
    float  *p_hmid, *p_asrc1, *p_adst1, *p_asrc2, *p_adst2;
    cudaGetSymbolAddress((void**)&p_h1h,   g_h1h);
    cudaGetSymbolAddress((void**)&p_hmid,  g_hmid);
    cudaGetSymbolAddress((void**)&p_h2h,   g_h2h);
    cudaGetSymbolAddress((void**)&p_asrc1, g_asrc1);
    cudaGetSymbolAddress((void**)&p_adst1, g_adst1);
    cudaGetSymbolAddress((void**)&p_asrc2, g_asrc2);
    cudaGetSymbolAddress((void**)&p_adst2, g_adst2);

    // ---- CSR build prefix + big GEMM early ----
    init_deg_kernel<<<(NN + 255) / 256, 256>>>();            // 0
    histrank_kernel<<<(E + 255) / 256, 256>>>(edst, E);      // 1
    scan_fused_kernel<<<1, 1024>>>();                        // 2
    {
        dim3 grid((NH * HF1) / 128, (NN + 127) / 128);       // 3  <- profiled
        gemm_tc_kernel<<<grid, 256>>>(x, W1, p_h1h, NN, INF, NH * HF1);
    }
    scatter_kernel<<<(E + NN + 255) / 256, 256>>>(esrc, edst, E);  // 4

    // ---- layer 1 ----
    att_kernel<<<NN, 256>>>(p_h1h, as1, ad1, p_asrc1, p_adst1, HF1);
    agg_kernel<HF1><<<NN, 256>>>(p_h1h, p_asrc1, p_adst1, b1, p_hmid, 1);

    // ---- layer 2 ----
    {
        dim3 grid((NH * OUTC) / 128, (NN + 127) / 128);
        gemm_tc_kernel<<<grid, 256>>>(p_hmid, W2, p_h2h, NN, HF1, NH * OUTC);
    }
    att_kernel<<<NN, 256>>>(p_h2h, as2, ad2, p_asrc2, p_adst2, OUTC);
    agg_kernel<OUTC><<<NN, 256>>>(p_h2h, p_asrc2, p_adst2, b2, out, 0);
}